// round 13
// baseline (speedup 1.0000x reference)
#include <cuda_runtime.h>
#include <cuda_fp16.h>
#include <math.h>
#include <stdint.h>

// Problem constants (fixed: B=4, N=2048, DIM=512, H=1)
#define CB 4
#define CN 2048
#define CD 512
#define C5 (5 * CD)   // 2560
#define C2 (2 * CD)   // 1024
#define DNROWS (CB * CN)

// Proven 8-warp tile: 128x128x(32 f16 | 64 f8), 4-stage, 2 CTAs/SM
#define BM 128
#define BN 128
#define BK 32
#define TILE_B (128 * 80)
#define STAGE_B (2 * TILE_B)
#define NST 4
#define SMEM_G (NST * STAGE_B)       // 81920 B
#define SBNN 272                     // NN B smem row stride (bytes, fp16 path)

typedef __half f16;

// ---------------------------------------------------------------------------
// Scratch (__device__ globals)
// ---------------------------------------------------------------------------
static __device__ f16     g_x16 [(size_t)CB * CN * CD];
static __device__ f16     g_w16 [(size_t)C5 * CD];
static __device__ f16     g_ow16[(size_t)CD * C2];
static __device__ f16     g_P16 [(size_t)CB * CN * C5];
static __device__ f16     g_S   [(size_t)3 * CB * CN * CN];   // X | Y | Zt (fp16)
static __device__ uint8_t g_S8  [(size_t)3 * CB * CN * CN];   // X8 | Y8 | Zt8 (e4m3)
static __device__ uint8_t g_Yt8 [(size_t)CB * CN * CN];       // Y8 transposed
static __device__ f16     g_M   [(size_t)2 * CB * CN * CN];   // M1 | M2
static __device__ float   g_dnp [(size_t)32 * DNROWS];
static __device__ float   g_dn  [(size_t)DNROWS];
static __device__ f16     g_u16 [(size_t)CB * CN * C2];

// ---------------------------------------------------------------------------
// PTX helpers
// ---------------------------------------------------------------------------
__device__ __forceinline__ uint32_t smem_u32(const void* p) {
    return (uint32_t)__cvta_generic_to_shared(p);
}
__device__ __forceinline__ void cp16(uint32_t s, const void* g) {
    asm volatile("cp.async.cg.shared.global [%0], [%1], 16;\n" :: "r"(s), "l"(g));
}
__device__ __forceinline__ void ldsm4(uint32_t& r0, uint32_t& r1, uint32_t& r2,
                                      uint32_t& r3, uint32_t a) {
    asm volatile("ldmatrix.sync.aligned.m8n8.x4.shared.b16 {%0,%1,%2,%3}, [%4];"
        : "=r"(r0), "=r"(r1), "=r"(r2), "=r"(r3) : "r"(a));
}
__device__ __forceinline__ void ldsm4t(uint32_t& r0, uint32_t& r1, uint32_t& r2,
                                       uint32_t& r3, uint32_t a) {
    asm volatile("ldmatrix.sync.aligned.m8n8.x4.trans.shared.b16 {%0,%1,%2,%3}, [%4];"
        : "=r"(r0), "=r"(r1), "=r"(r2), "=r"(r3) : "r"(a));
}
__device__ __forceinline__ void mma16(float* c, const uint32_t* a, const uint32_t* b) {
    asm volatile(
        "mma.sync.aligned.m16n8k16.row.col.f32.f16.f16.f32 "
        "{%0,%1,%2,%3}, {%4,%5,%6,%7}, {%8,%9}, {%0,%1,%2,%3};\n"
        : "+f"(c[0]), "+f"(c[1]), "+f"(c[2]), "+f"(c[3])
        : "r"(a[0]), "r"(a[1]), "r"(a[2]), "r"(a[3]), "r"(b[0]), "r"(b[1]));
}
__device__ __forceinline__ void mma8(float* c, const uint32_t* a, const uint32_t* b) {
    asm volatile(
        "mma.sync.aligned.m16n8k32.row.col.f32.e4m3.e4m3.f32 "
        "{%0,%1,%2,%3}, {%4,%5,%6,%7}, {%8,%9}, {%0,%1,%2,%3};\n"
        : "+f"(c[0]), "+f"(c[1]), "+f"(c[2]), "+f"(c[3])
        : "r"(a[0]), "r"(a[1]), "r"(a[2]), "r"(a[3]), "r"(b[0]), "r"(b[1]));
}
__device__ __forceinline__ uint32_t pack_h2(float x, float y) {
    uint32_t r; asm("cvt.rn.f16x2.f32 %0, %1, %2;" : "=r"(r) : "f"(y), "f"(x));
    return r;
}
__device__ __forceinline__ uint16_t pack_e4(float x, float y) {
    uint16_t r;
    asm("cvt.rn.satfinite.e4m3x2.f32 %0, %1, %2;" : "=h"(r) : "f"(y), "f"(x));
    return r;
}

// ---------------------------------------------------------------------------
// 8-warp fp16 GEMM (proven): 128x128x32, 32x64 warp tiles, 2 CTAs/SM.
// MODE 0: batched z; MODE 1: merged score GEMMs (+ optional fp8 dual-write);
// MODE 2: merged u GEMMs (NN + DIV by den).
// ---------------------------------------------------------------------------
template <int MODE, bool NN, bool EXP, bool BIAS, bool DIV, bool F8, typename OutT>
__global__ __launch_bounds__(256, 2)
void gemm16(const f16* __restrict__ A, const f16* __restrict__ B,
            OutT* __restrict__ C, uint8_t* __restrict__ C8,
            const float* __restrict__ den,
            int K, int lda, int ldb, int ldc,
            size_t sA, size_t sB, size_t sC,
            float escale, const float* __restrict__ bias)
{
    extern __shared__ char dyn[];
    const uint32_t sm0 = smem_u32(dyn);
    const int tid  = threadIdx.x;
    const int lane = tid & 31;
    const int warp = tid >> 5;
    const int m0   = blockIdx.y * BM;
    const int n0   = blockIdx.x * BN;
    const int mb   = (warp & 3) * 32;
    const int wn   = warp >> 2;
    const int nb   = wn * 64;

    const int zb = blockIdx.z;
    if (MODE == 1) {
        const int op = zb >> 2, b = zb & 3;
        A += ((op == 1) ? CD : 0) + (size_t)b * sA;
        B += ((op == 0) ? CD : 2 * CD) + (size_t)b * sB;
        C += (size_t)(op * 4 + b) * sC;
        if (F8) C8 += (size_t)(op * 4 + b) * sC;
    } else if (MODE == 2) {
        const int op = zb >> 2, b = zb & 3;
        A += (size_t)(op * 4 + b) * sA;
        B += (3 + op) * CD + (size_t)b * sB;
        C += (size_t)op * CD + (size_t)b * sC;
        den += (size_t)b * CN;
    } else {
        A += (size_t)zb * sA;
        B += (size_t)zb * sB;
        C += (size_t)zb * sC;
    }
    A += (size_t)m0 * lda;
    if (NN) B += n0;
    else    B += (size_t)n0 * ldb;

    float acc[2][8][4];
#pragma unroll
    for (int mt = 0; mt < 2; mt++)
#pragma unroll
        for (int nt = 0; nt < 8; nt++)
#pragma unroll
            for (int r = 0; r < 4; r++) acc[mt][nt][r] = 0.f;

    auto load_stage = [&](int st, int ch) {
        const uint32_t sa = sm0 + st * STAGE_B;
        const uint32_t sb = sa + TILE_B;
        const f16* ga = A + ch * BK;
#pragma unroll
        for (int t = 0; t < 2; t++) {
            int idx = t * 256 + tid;
            int r = idx >> 2, c = idx & 3;
            cp16(sa + r * 80 + c * 16, ga + (size_t)r * lda + c * 8);
        }
        if (NN) {
            const f16* gb = B + (size_t)(ch * BK) * ldb;
#pragma unroll
            for (int t = 0; t < 2; t++) {
                int idx = t * 256 + tid;
                int r = idx >> 4, c = idx & 15;
                cp16(sb + r * SBNN + c * 16, gb + (size_t)r * ldb + c * 8);
            }
        } else {
            const f16* gb = B + ch * BK;
#pragma unroll
            for (int t = 0; t < 2; t++) {
                int idx = t * 256 + tid;
                int r = idx >> 2, c = idx & 3;
                cp16(sb + r * 80 + c * 16, gb + (size_t)r * ldb + c * 8);
            }
        }
        asm volatile("cp.async.commit_group;\n");
    };

    auto compute_stage = [&](int st) {
        const uint32_t sa = sm0 + st * STAGE_B;
        const uint32_t sb = sa + TILE_B;
#pragma unroll
        for (int ks = 0; ks < 2; ks++) {
            const int k0 = ks * 16;
            uint32_t a[2][4];
#pragma unroll
            for (int mt = 0; mt < 2; mt++) {
                int row = mb + mt * 16 + (lane & 7) + ((lane >> 3) & 1) * 8;
                int col = k0 + ((lane >> 4) & 1) * 8;
                ldsm4(a[mt][0], a[mt][1], a[mt][2], a[mt][3], sa + row * 80 + col * 2);
            }
            uint32_t b[8][2];
#pragma unroll
            for (int jp = 0; jp < 4; jp++) {
                if (NN) {
                    int krow = (lane & 7) + ((lane >> 3) & 1) * 8;
                    int ncol = nb + jp * 16 + ((lane >> 4) & 1) * 8;
                    ldsm4t(b[2 * jp][0], b[2 * jp][1], b[2 * jp + 1][0], b[2 * jp + 1][1],
                           sb + (k0 + krow) * SBNN + ncol * 2);
                } else {
                    int row = nb + jp * 16 + (lane & 7) + ((lane >> 4) & 1) * 8;
                    int col = k0 + ((lane >> 3) & 1) * 8;
                    ldsm4(b[2 * jp][0], b[2 * jp][1], b[2 * jp + 1][0], b[2 * jp + 1][1],
                          sb + row * 80 + col * 2);
                }
            }
#pragma unroll
            for (int mt = 0; mt < 2; mt++)
#pragma unroll
                for (int nt = 0; nt < 8; nt++)
                    mma16(acc[mt][nt], a[mt], b[nt]);
        }
    };

    const int nc = K / BK;
    load_stage(0, 0);
    load_stage(1, 1);
    load_stage(2, 2);
    for (int ch = 0; ch < nc; ch++) {
        if (ch < nc - 2)       asm volatile("cp.async.wait_group 2;\n");
        else if (ch == nc - 2) asm volatile("cp.async.wait_group 1;\n");
        else                   asm volatile("cp.async.wait_group 0;\n");
        __syncthreads();
        compute_stage(ch & 3);
        if (ch + 3 < nc) load_stage((ch + 3) & 3, ch + 3);
    }

    const int r0 = m0 + mb + (lane >> 2);
    const int c0 = n0 + nb + 2 * (lane & 3);
    float rd[2][2];
    if (DIV) {
#pragma unroll
        for (int mt = 0; mt < 2; mt++)
#pragma unroll
            for (int h = 0; h < 2; h++)
                rd[mt][h] = 1.0f / den[r0 + mt * 16 + 8 * h];
    }
#pragma unroll
    for (int mt = 0; mt < 2; mt++) {
#pragma unroll
        for (int nt = 0; nt < 8; nt++) {
            const int row = r0 + mt * 16;
            const int col = c0 + nt * 8;
            float v0 = acc[mt][nt][0], v1 = acc[mt][nt][1];
            float v2 = acc[mt][nt][2], v3 = acc[mt][nt][3];
            if (EXP) {
                v0 = __expf(escale * v0); v1 = __expf(escale * v1);
                v2 = __expf(escale * v2); v3 = __expf(escale * v3);
            }
            if (BIAS) {
                const float b0 = bias[col], b1 = bias[col + 1];
                v0 += b0; v1 += b1; v2 += b0; v3 += b1;
            }
            if (DIV) {
                v0 *= rd[mt][0]; v1 *= rd[mt][0];
                v2 *= rd[mt][1]; v3 *= rd[mt][1];
            }
            if (sizeof(OutT) == 2) {
                f16* p = (f16*)C;
                *reinterpret_cast<uint32_t*>(p + (size_t)row * ldc + col)       = pack_h2(v0, v1);
                *reinterpret_cast<uint32_t*>(p + (size_t)(row + 8) * ldc + col) = pack_h2(v2, v3);
            } else {
                float* p = (float*)C;
                *reinterpret_cast<float2*>(p + (size_t)row * ldc + col)       = make_float2(v0, v1);
                *reinterpret_cast<float2*>(p + (size_t)(row + 8) * ldc + col) = make_float2(v2, v3);
            }
            if (F8) {
                *reinterpret_cast<uint16_t*>(C8 + (size_t)row * ldc + col)       = pack_e4(v0, v1);
                *reinterpret_cast<uint16_t*>(C8 + (size_t)(row + 8) * ldc + col) = pack_e4(v2, v3);
            }
        }
    }
}

// ---------------------------------------------------------------------------
// fp8 e4m3 NT GEMM for the two N^3 products: 128x128x64(e4m3), 4-stage,
// 2 CTAs/SM. Fragment topology identical to fp16 (b16 slot = 2 fp8), so
// same 80B-stride smem layout and same ldsm4 — but each k-chunk is 64
// elements and each mma covers k=32: HALF the MMA count of the fp16 path.
// C[i,j] = (sum_k A[i,k]*B[j,k]) * Mul[i,j]; optional row partials -> dnp.
// ---------------------------------------------------------------------------
template <bool DEN>
__global__ __launch_bounds__(256, 2)
void gemm8(const uint8_t* __restrict__ A, const uint8_t* __restrict__ B,
           f16* __restrict__ C, const f16* __restrict__ Mul,
           float* __restrict__ dnp,
           int K, int lda, int ldb, int ldc,
           size_t sA, size_t sB, size_t sC)
{
    extern __shared__ char dyn[];
    const uint32_t sm0 = smem_u32(dyn);
    const int tid  = threadIdx.x;
    const int lane = tid & 31;
    const int warp = tid >> 5;
    const int m0   = blockIdx.y * BM;
    const int n0   = blockIdx.x * BN;
    const int mb   = (warp & 3) * 32;
    const int wn   = warp >> 2;
    const int nb   = wn * 64;
    const int zb   = blockIdx.z;

    A += (size_t)zb * sA + (size_t)m0 * lda;
    B += (size_t)zb * sB + (size_t)n0 * ldb;
    C += (size_t)zb * sC;
    Mul += (size_t)zb * sC;

    float acc[2][8][4];
#pragma unroll
    for (int mt = 0; mt < 2; mt++)
#pragma unroll
        for (int nt = 0; nt < 8; nt++)
#pragma unroll
            for (int r = 0; r < 4; r++) acc[mt][nt][r] = 0.f;

    auto load_stage = [&](int st, int ch) {
        const uint32_t sa = sm0 + st * STAGE_B;
        const uint32_t sb = sa + TILE_B;
        const uint8_t* ga = A + ch * 64;
        const uint8_t* gb = B + ch * 64;
#pragma unroll
        for (int t = 0; t < 2; t++) {          // 128 rows x 4 x 16B (= 64 fp8)
            int idx = t * 256 + tid;
            int r = idx >> 2, c = idx & 3;
            cp16(sa + r * 80 + c * 16, ga + (size_t)r * lda + c * 16);
            cp16(sb + r * 80 + c * 16, gb + (size_t)r * ldb + c * 16);
        }
        asm volatile("cp.async.commit_group;\n");
    };

    auto compute_stage = [&](int st) {
        const uint32_t sa = sm0 + st * STAGE_B;
        const uint32_t sb = sa + TILE_B;
#pragma unroll
        for (int ks = 0; ks < 2; ks++) {
            const int k0b = ks * 32;           // byte offset of this k=32 slice
            uint32_t a[2][4];
#pragma unroll
            for (int mt = 0; mt < 2; mt++) {
                int row = mb + mt * 16 + (lane & 7) + ((lane >> 3) & 1) * 8;
                int colb = k0b + ((lane >> 4) & 1) * 16;
                ldsm4(a[mt][0], a[mt][1], a[mt][2], a[mt][3], sa + row * 80 + colb);
            }
            uint32_t b[8][2];
#pragma unroll
            for (int jp = 0; jp < 4; jp++) {
                int row = nb + jp * 16 + (lane & 7) + ((lane >> 4) & 1) * 8;
                int colb = k0b + ((lane >> 3) & 1) * 16;
                ldsm4(b[2 * jp][0], b[2 * jp][1], b[2 * jp + 1][0], b[2 * jp + 1][1],
                      sb + row * 80 + colb);
            }
#pragma unroll
            for (int mt = 0; mt < 2; mt++)
#pragma unroll
                for (int nt = 0; nt < 8; nt++)
                    mma8(acc[mt][nt], a[mt], b[nt]);
        }
    };

    const int nc = K / 64;    // 32 chunks for K=2048
    load_stage(0, 0);
    load_stage(1, 1);
    load_stage(2, 2);
    for (int ch = 0; ch < nc; ch++) {
        if (ch < nc - 2)       asm volatile("cp.async.wait_group 2;\n");
        else if (ch == nc - 2) asm volatile("cp.async.wait_group 1;\n");
        else                   asm volatile("cp.async.wait_group 0;\n");
        __syncthreads();
        compute_stage(ch & 3);
        if (ch + 3 < nc) load_stage((ch + 3) & 3, ch + 3);
    }

    // Epilogue: multiply by fp16 Mul, write fp16, optional den partials
    const int r0 = m0 + mb + (lane >> 2);
    const int c0 = n0 + nb + 2 * (lane & 3);
    float dsum[2][2];
    if (DEN) {
#pragma unroll
        for (int mt = 0; mt < 2; mt++) { dsum[mt][0] = 0.f; dsum[mt][1] = 0.f; }
    }
#pragma unroll
    for (int mt = 0; mt < 2; mt++) {
#pragma unroll
        for (int nt = 0; nt < 8; nt++) {
            const int row = r0 + mt * 16;
            const int col = c0 + nt * 8;
            float v0 = acc[mt][nt][0], v1 = acc[mt][nt][1];
            float v2 = acc[mt][nt][2], v3 = acc[mt][nt][3];
            float2 ma = __half22float2(
                *reinterpret_cast<const __half2*>(Mul + (size_t)row * ldc + col));
            float2 mb2 = __half22float2(
                *reinterpret_cast<const __half2*>(Mul + (size_t)(row + 8) * ldc + col));
            v0 *= ma.x; v1 *= ma.y; v2 *= mb2.x; v3 *= mb2.y;
            if (DEN) {
                dsum[mt][0] += v0 + v1;
                dsum[mt][1] += v2 + v3;
            }
            *reinterpret_cast<uint32_t*>(C + (size_t)row * ldc + col)       = pack_h2(v0, v1);
            *reinterpret_cast<uint32_t*>(C + (size_t)(row + 8) * ldc + col) = pack_h2(v2, v3);
        }
    }
    if (DEN) {
        const int p = blockIdx.x * 2 + wn;
#pragma unroll
        for (int mt = 0; mt < 2; mt++) {
#pragma unroll
            for (int h = 0; h < 2; h++) {
                float s = dsum[mt][h];
                s += __shfl_xor_sync(0xffffffffu, s, 1);
                s += __shfl_xor_sync(0xffffffffu, s, 2);
                if ((lane & 3) == 0) {
                    const int grow = zb * (gridDim.y * BM) + r0 + mt * 16 + 8 * h;
                    dnp[(size_t)p * DNROWS + grow] = s;
                }
            }
        }
    }
}

// ---------------------------------------------------------------------------
__global__ void prep_k(const float* __restrict__ x, const float* __restrict__ w,
                       const float* __restrict__ ow, f16* __restrict__ x16,
                       f16* __restrict__ w16, f16* __restrict__ ow16)
{
    const size_t Sx = (size_t)CB * CN * CD;
    const size_t Sw = (size_t)C5 * CD;
    const size_t So = (size_t)CD * C2;
    const size_t total = Sx + Sw + So;
    for (size_t i = (size_t)blockIdx.x * blockDim.x + threadIdx.x; i < total;
         i += (size_t)gridDim.x * blockDim.x) {
        if (i < Sx)           x16[i]            = __float2half_rn(x[i]);
        else if (i < Sx + Sw) w16[i - Sx]       = __float2half_rn(w[i - Sx]);
        else                  ow16[i - Sx - Sw] = __float2half_rn(ow[i - Sx - Sw]);
    }
}

// fp8 byte transpose: dst[b][c][r] = src[b][r][c]
__global__ void tr8_k(const uint8_t* __restrict__ src, uint8_t* __restrict__ dst)
{
    __shared__ uint8_t t[32][33];
    const int b  = blockIdx.z;
    const int c0 = blockIdx.x * 32;
    const int r0 = blockIdx.y * 32;
    const int tx = threadIdx.x, ty = threadIdx.y;
    src += (size_t)b * CN * CN;
    dst += (size_t)b * CN * CN;
#pragma unroll
    for (int k = 0; k < 4; k++)
        t[ty + 8 * k][tx] = src[(size_t)(r0 + ty + 8 * k) * CN + c0 + tx];
    __syncthreads();
#pragma unroll
    for (int k = 0; k < 4; k++)
        dst[(size_t)(c0 + ty + 8 * k) * CN + r0 + tx] = t[tx][ty + 8 * k];
}

// den[r] = sum_p dnp[p][r]  (deterministic fixed-order sum)
__global__ void dnred_k(const float* __restrict__ dnp, float* __restrict__ dn)
{
    const int r = blockIdx.x * blockDim.x + threadIdx.x;
    if (r < DNROWS) {
        float s = 0.f;
#pragma unroll
        for (int p = 0; p < 32; p++) s += dnp[(size_t)p * DNROWS + r];
        dn[r] = s;
    }
}

// ---------------------------------------------------------------------------
extern "C" void kernel_launch(void* const* d_in, const int* in_sizes, int n_in,
                              void* d_out, int out_size)
{
    const float* x  = (const float*)d_in[0];
    const float* w  = (const float*)d_in[1];
    const float* ow = (const float*)d_in[2];
    const float* ob = (const float*)d_in[3];
    float* out = (float*)d_out;

    f16 *x16, *w16, *ow16, *P16, *S, *M, *u16;
    uint8_t *S8, *Yt8;
    float *dnp, *dn;
    cudaGetSymbolAddress((void**)&x16,  g_x16);
    cudaGetSymbolAddress((void**)&w16,  g_w16);
    cudaGetSymbolAddress((void**)&ow16, g_ow16);
    cudaGetSymbolAddress((void**)&P16,  g_P16);
    cudaGetSymbolAddress((void**)&S,    g_S);
    cudaGetSymbolAddress((void**)&S8,   g_S8);
    cudaGetSymbolAddress((void**)&Yt8,  g_Yt8);
    cudaGetSymbolAddress((void**)&M,    g_M);
    cudaGetSymbolAddress((void**)&dnp,  g_dnp);
    cudaGetSymbolAddress((void**)&dn,   g_dn);
    cudaGetSymbolAddress((void**)&u16,  g_u16);

    const size_t sP  = (size_t)CN * C5;
    const size_t sNN = (size_t)CN * CN;
    f16* X16v = S;
    f16* Zt16v = S + (size_t)2 * CB * sNN;
    uint8_t* X8  = S8;
    uint8_t* Y8  = S8 + (size_t)CB * sNN;
    uint8_t* Zt8 = S8 + (size_t)2 * CB * sNN;
    f16* M1 = M;
    f16* M2 = M + (size_t)CB * sNN;

    cudaFuncSetAttribute(gemm16<0, false, false, false, false, false, f16>,
                         cudaFuncAttributeMaxDynamicSharedMemorySize, SMEM_G);
    cudaFuncSetAttribute(gemm16<1, false, true, false, false, true, f16>,
                         cudaFuncAttributeMaxDynamicSharedMemorySize, SMEM_G);
    cudaFuncSetAttribute(gemm8<false>,
                         cudaFuncAttributeMaxDynamicSharedMemorySize, SMEM_G);
    cudaFuncSetAttribute(gemm8<true>,
                         cudaFuncAttributeMaxDynamicSharedMemorySize, SMEM_G);
    cudaFuncSetAttribute(gemm16<2, true, false, false, true, false, f16>,
                         cudaFuncAttributeMaxDynamicSharedMemorySize, SMEM_G);
    cudaFuncSetAttribute(gemm16<0, false, false, true, false, false, float>,
                         cudaFuncAttributeMaxDynamicSharedMemorySize, SMEM_G);

    const float scale = 1.0f / sqrtf((float)CD);

    // 0. round inputs to fp16
    prep_k<<<592, 256>>>(x, w, ow, x16, w16, ow16);

    // 1. P = x @ w^T   (NT, fp16 out)
    gemm16<0, false, false, false, false, false, f16>
        <<<dim3(C5 / BN, (CB * CN) / BM, 1), 256, SMEM_G>>>(
        x16, w16, P16, nullptr, nullptr,
        CD, CD, CD, C5, 0, 0, 0, 1.f, nullptr);

    // 2. Merged scores, dual fp16 + e4m3 output:
    //    op0 X=exp(s a·b^T), op1 Y=exp(s b·c^T), op2 Zt=exp(s a·c^T)
    gemm16<1, false, true, false, false, true, f16>
        <<<dim3(CN / BN, CN / BM, 3 * CB), 256, SMEM_G>>>(
        P16, P16, S, S8, nullptr,
        CD, C5, C5, CN, sP, sP, sNN, scale, nullptr);

    // 3. Yt8 = transpose(Y8)
    tr8_k<<<dim3(CN / 32, CN / 32, CB), dim3(32, 8)>>>(Y8, Yt8);

    // 4. M2 = NT8(X8, Yt8) .* Zt16   (= (X@Y) .* Zt, fp8 tensor path)
    gemm8<false><<<dim3(CN / BN, CN / BM, CB), 256, SMEM_G>>>(
        X8, Yt8, M2, Zt16v, nullptr,
        CN, CN, CN, CN, sNN, sNN, sNN);

    // 5. M1 = NT8(Zt8, Y8) .* X16 + row partials -> dnp
    gemm8<true><<<dim3(CN / BN, CN / BM, CB), 256, SMEM_G>>>(
        Zt8, Y8, M1, X16v, dnp,
        CN, CN, CN, CN, sNN, sNN, sNN);

    // 6. den = reduce(dnp)
    dnred_k<<<(DNROWS + 255) / 256, 256>>>(dnp, dn);

    // 7. Merged u: op0 u[:, :512] = (M1@v1)/den, op1 u[:, 512:] = (M2@v2)/den
    gemm16<2, true, false, false, true, false, f16>
        <<<dim3(CD / BN, CN / BM, 2 * CB), 256, SMEM_G>>>(
        M, P16, u16, nullptr, dn,
        CN, CN, C5, C2, sNN, sP, (size_t)CN * C2, 1.f, nullptr);

    // 8. out = NT(u, ow) + ob   (f32 out)
    gemm16<0, false, false, true, false, false, float>
        <<<dim3(CD / BN, (CB * CN) / BM, 1), 256, SMEM_G>>>(
        u16, ow16, out, nullptr, nullptr,
        C2, C2, C2, CD, 0, 0, 0, 1.f, ob);
}

// round 16
// speedup vs baseline: 1.1116x; 1.1116x over previous
#include <cuda_runtime.h>
#include <cuda_fp16.h>
#include <math.h>
#include <stdint.h>

// Problem constants (fixed: B=4, N=2048, DIM=512, H=1)
#define CB 4
#define CN 2048
#define CD 512
#define C5 (5 * CD)   // 2560
#define C2 (2 * CD)   // 1024
#define DNROWS (CB * CN)

#define BM 128
#define BN 128
#define BK64 64
#define TA64 (128 * 144)             // NT operand tile: 18432 B (NN B: 64*272=17408 fits)
#define STAGE64 (2 * TA64)           // 36864 B
#define SMEM_64 (3 * STAGE64)        // 110592 B -> 2 CTAs/SM (221184 <= 228KB)
#define SBNN 272                     // NN B smem row stride (bytes)

typedef __half f16;

// ---------------------------------------------------------------------------
// Scratch (__device__ globals)
// ---------------------------------------------------------------------------
static __device__ f16   g_x16 [(size_t)CB * CN * CD];
static __device__ f16   g_w16 [(size_t)C5 * CD];
static __device__ f16   g_ow16[(size_t)CD * C2];
static __device__ f16   g_P16 [(size_t)CB * CN * C5];
static __device__ f16   g_S   [(size_t)3 * CB * CN * CN];   // X | Y | Zt
static __device__ f16   g_M   [(size_t)2 * CB * CN * CN];   // M1 | M2
static __device__ float g_dnp [(size_t)32 * DNROWS];
static __device__ float g_dn  [(size_t)DNROWS];
static __device__ f16   g_u16 [(size_t)CB * CN * C2];

// ---------------------------------------------------------------------------
// PTX helpers
// ---------------------------------------------------------------------------
__device__ __forceinline__ uint32_t smem_u32(const void* p) {
    return (uint32_t)__cvta_generic_to_shared(p);
}
__device__ __forceinline__ void cp16(uint32_t s, const void* g) {
    asm volatile("cp.async.cg.shared.global [%0], [%1], 16;\n" :: "r"(s), "l"(g));
}
__device__ __forceinline__ void ldsm4(uint32_t& r0, uint32_t& r1, uint32_t& r2,
                                      uint32_t& r3, uint32_t a) {
    asm volatile("ldmatrix.sync.aligned.m8n8.x4.shared.b16 {%0,%1,%2,%3}, [%4];"
        : "=r"(r0), "=r"(r1), "=r"(r2), "=r"(r3) : "r"(a));
}
__device__ __forceinline__ void ldsm4t(uint32_t& r0, uint32_t& r1, uint32_t& r2,
                                       uint32_t& r3, uint32_t a) {
    asm volatile("ldmatrix.sync.aligned.m8n8.x4.trans.shared.b16 {%0,%1,%2,%3}, [%4];"
        : "=r"(r0), "=r"(r1), "=r"(r2), "=r"(r3) : "r"(a));
}
__device__ __forceinline__ void mma16(float* c, const uint32_t* a, const uint32_t* b) {
    asm volatile(
        "mma.sync.aligned.m16n8k16.row.col.f32.f16.f16.f32 "
        "{%0,%1,%2,%3}, {%4,%5,%6,%7}, {%8,%9}, {%0,%1,%2,%3};\n"
        : "+f"(c[0]), "+f"(c[1]), "+f"(c[2]), "+f"(c[3])
        : "r"(a[0]), "r"(a[1]), "r"(a[2]), "r"(a[3]), "r"(b[0]), "r"(b[1]));
}
__device__ __forceinline__ uint32_t pack_h2(float x, float y) {
    uint32_t r; asm("cvt.rn.f16x2.f32 %0, %1, %2;" : "=r"(r) : "f"(y), "f"(x));
    return r;
}

// ---------------------------------------------------------------------------
// Unified BK=64 3-stage fp16 GEMM: 128x128x64, 8 warps (32x64), 2 CTAs/SM.
// Base: C[i,j] = sum_k A[i,k] * op(B), fp32 accum.
//   NN=false: op(B)=B[j,k] (NT, stride-144 smem);  NN=true: op(B)=B[k,j]
//   (NN, k-major B, stride-272 smem, trans-ldsm).
// MODE 0: batched via blockIdx.z (strides sA/sB/sC; MULT also strided)
// MODE 1: merged score GEMMs (z=op*4+b; A/B = P slices; C = S[op][b])
// MODE 2: merged u GEMMs (z=op*4+b; A=M[op][b]; B=P v-slice; C=u cols; DIV)
// EXP: exp(escale*v)  BIAS: +bias[col]  MULT: *=Mul[i,j]  DEN: partials->dnp
// REQUIRES: M,N mult 128; K mult 64; lda/ldb mult 8.
// ---------------------------------------------------------------------------
template <int MODE, bool NN, bool EXP, bool BIAS, bool MULT, bool DEN, bool DIV, typename OutT>
__global__ __launch_bounds__(256, 2)
void gemm64(const f16* __restrict__ A, const f16* __restrict__ B,
            OutT* __restrict__ C, const f16* __restrict__ Mul,
            float* __restrict__ dnp, const float* __restrict__ den,
            int K, int lda, int ldb, int ldc,
            size_t sA, size_t sB, size_t sC,
            float escale, const float* __restrict__ bias)
{
    extern __shared__ char dyn[];
    const uint32_t sm0 = smem_u32(dyn);
    const int tid  = threadIdx.x;
    const int lane = tid & 31;
    const int warp = tid >> 5;
    const int m0   = blockIdx.y * BM;
    const int n0   = blockIdx.x * BN;
    const int mb   = (warp & 3) * 32;
    const int wn   = warp >> 2;
    const int nb   = wn * 64;

    const int zb = blockIdx.z;
    if (MODE == 1) {
        const int op = zb >> 2, b = zb & 3;
        A += ((op == 1) ? CD : 0) + (size_t)b * sA;
        B += ((op == 0) ? CD : 2 * CD) + (size_t)b * sB;
        C += (size_t)(op * 4 + b) * sC;
    } else if (MODE == 2) {
        const int op = zb >> 2, b = zb & 3;
        A += (size_t)(op * 4 + b) * sA;
        B += (3 + op) * CD + (size_t)b * sB;
        C += (size_t)op * CD + (size_t)b * sC;
        den += (size_t)b * CN;
    } else {
        A += (size_t)zb * sA;
        B += (size_t)zb * sB;
        C += (size_t)zb * sC;
        if (MULT) Mul += (size_t)zb * sC;
    }
    A += (size_t)m0 * lda;
    if (NN) B += n0;
    else    B += (size_t)n0 * ldb;

    float acc[2][8][4];
#pragma unroll
    for (int mt = 0; mt < 2; mt++)
#pragma unroll
        for (int nt = 0; nt < 8; nt++)
#pragma unroll
            for (int r = 0; r < 4; r++) acc[mt][nt][r] = 0.f;

    auto load_stage = [&](int st, int ch) {
        const uint32_t sa = sm0 + st * STAGE64;
        const uint32_t sb = sa + TA64;
        const f16* ga = A + ch * BK64;
#pragma unroll
        for (int t = 0; t < 4; t++) {           // A: 128 rows x 8 x 16B
            int idx = t * 256 + tid;
            int r = idx >> 3, c = idx & 7;
            cp16(sa + r * 144 + c * 16, ga + (size_t)r * lda + c * 8);
        }
        if (NN) {
            const f16* gb = B + (size_t)(ch * BK64) * ldb;
#pragma unroll
            for (int t = 0; t < 4; t++) {       // B: 64 k-rows x 16 x 16B
                int idx = t * 256 + tid;
                int r = idx >> 4, c = idx & 15;
                cp16(sb + r * SBNN + c * 16, gb + (size_t)r * ldb + c * 8);
            }
        } else {
            const f16* gb = B + ch * BK64;
#pragma unroll
            for (int t = 0; t < 4; t++) {       // B: 128 n-rows x 8 x 16B
                int idx = t * 256 + tid;
                int r = idx >> 3, c = idx & 7;
                cp16(sb + r * 144 + c * 16, gb + (size_t)r * ldb + c * 8);
            }
        }
        asm volatile("cp.async.commit_group;\n");
    };

    auto compute_stage = [&](int st) {
        const uint32_t sa = sm0 + st * STAGE64;
        const uint32_t sb = sa + TA64;
#pragma unroll
        for (int ks = 0; ks < 4; ks++) {
            const int k0 = ks * 16;
            uint32_t a[2][4];
#pragma unroll
            for (int mt = 0; mt < 2; mt++) {
                int row = mb + mt * 16 + (lane & 7) + ((lane >> 3) & 1) * 8;
                int col = k0 + ((lane >> 4) & 1) * 8;
                ldsm4(a[mt][0], a[mt][1], a[mt][2], a[mt][3], sa + row * 144 + col * 2);
            }
            uint32_t b[8][2];
#pragma unroll
            for (int jp = 0; jp < 4; jp++) {
                if (NN) {
                    int krow = (lane & 7) + ((lane >> 3) & 1) * 8;
                    int ncol = nb + jp * 16 + ((lane >> 4) & 1) * 8;
                    ldsm4t(b[2 * jp][0], b[2 * jp][1], b[2 * jp + 1][0], b[2 * jp + 1][1],
                           sb + (k0 + krow) * SBNN + ncol * 2);
                } else {
                    int row = nb + jp * 16 + (lane & 7) + ((lane >> 4) & 1) * 8;
                    int col = k0 + ((lane >> 3) & 1) * 8;
                    ldsm4(b[2 * jp][0], b[2 * jp][1], b[2 * jp + 1][0], b[2 * jp + 1][1],
                          sb + row * 144 + col * 2);
                }
            }
#pragma unroll
            for (int mt = 0; mt < 2; mt++)
#pragma unroll
                for (int nt = 0; nt < 8; nt++)
                    mma16(acc[mt][nt], a[mt], b[nt]);
        }
    };

    const int nc = K / BK64;    // >= 8 at all call sites
    load_stage(0, 0);
    load_stage(1, 1);
    for (int ch = 0; ch < nc; ch++) {
        if (ch < nc - 1) asm volatile("cp.async.wait_group 1;\n");
        else             asm volatile("cp.async.wait_group 0;\n");
        __syncthreads();
        compute_stage(ch % 3);
        if (ch + 2 < nc) load_stage((ch + 2) % 3, ch + 2);
    }

    // Epilogue
    const int r0 = m0 + mb + (lane >> 2);
    const int c0 = n0 + nb + 2 * (lane & 3);
    float rd[2][2];
    if (DIV) {
#pragma unroll
        for (int mt = 0; mt < 2; mt++)
#pragma unroll
            for (int h = 0; h < 2; h++)
                rd[mt][h] = 1.0f / den[r0 + mt * 16 + 8 * h];
    }
    float dsum[2][2];
    if (DEN) {
#pragma unroll
        for (int mt = 0; mt < 2; mt++) { dsum[mt][0] = 0.f; dsum[mt][1] = 0.f; }
    }
#pragma unroll
    for (int mt = 0; mt < 2; mt++) {
#pragma unroll
        for (int nt = 0; nt < 8; nt++) {
            const int row = r0 + mt * 16;
            const int col = c0 + nt * 8;
            float v0 = acc[mt][nt][0], v1 = acc[mt][nt][1];
            float v2 = acc[mt][nt][2], v3 = acc[mt][nt][3];
            if (EXP) {
                v0 = __expf(escale * v0); v1 = __expf(escale * v1);
                v2 = __expf(escale * v2); v3 = __expf(escale * v3);
            }
            if (BIAS) {
                const float b0 = bias[col], b1 = bias[col + 1];
                v0 += b0; v1 += b1; v2 += b0; v3 += b1;
            }
            if (MULT) {
                float2 ma = __half22float2(
                    *reinterpret_cast<const __half2*>(Mul + (size_t)row * ldc + col));
                float2 mb2 = __half22float2(
                    *reinterpret_cast<const __half2*>(Mul + (size_t)(row + 8) * ldc + col));
                v0 *= ma.x; v1 *= ma.y; v2 *= mb2.x; v3 *= mb2.y;
            }
            if (DIV) {
                v0 *= rd[mt][0]; v1 *= rd[mt][0];
                v2 *= rd[mt][1]; v3 *= rd[mt][1];
            }
            if (DEN) {
                dsum[mt][0] += v0 + v1;
                dsum[mt][1] += v2 + v3;
            }
            if (sizeof(OutT) == 2) {
                f16* p = (f16*)C;
                *reinterpret_cast<uint32_t*>(p + (size_t)row * ldc + col)       = pack_h2(v0, v1);
                *reinterpret_cast<uint32_t*>(p + (size_t)(row + 8) * ldc + col) = pack_h2(v2, v3);
            } else {
                float* p = (float*)C;
                *reinterpret_cast<float2*>(p + (size_t)row * ldc + col)       = make_float2(v0, v1);
                *reinterpret_cast<float2*>(p + (size_t)(row + 8) * ldc + col) = make_float2(v2, v3);
            }
        }
    }
    if (DEN) {
        // Deterministic partials: slice per (n-block, n-warp) = 16*2 = 32.
        const int p = blockIdx.x * 2 + wn;
#pragma unroll
        for (int mt = 0; mt < 2; mt++) {
#pragma unroll
            for (int h = 0; h < 2; h++) {
                float s = dsum[mt][h];
                s += __shfl_xor_sync(0xffffffffu, s, 1);
                s += __shfl_xor_sync(0xffffffffu, s, 2);
                if ((lane & 3) == 0) {
                    const int grow = zb * (gridDim.y * BM) + r0 + mt * 16 + 8 * h;
                    dnp[(size_t)p * DNROWS + grow] = s;
                }
            }
        }
    }
}

// ---------------------------------------------------------------------------
__global__ void prep_k(const float* __restrict__ x, const float* __restrict__ w,
                       const float* __restrict__ ow, f16* __restrict__ x16,
                       f16* __restrict__ w16, f16* __restrict__ ow16)
{
    const size_t Sx = (size_t)CB * CN * CD;
    const size_t Sw = (size_t)C5 * CD;
    const size_t So = (size_t)CD * C2;
    const size_t total = Sx + Sw + So;
    for (size_t i = (size_t)blockIdx.x * blockDim.x + threadIdx.x; i < total;
         i += (size_t)gridDim.x * blockDim.x) {
        if (i < Sx)           x16[i]            = __float2half_rn(x[i]);
        else if (i < Sx + Sw) w16[i - Sx]       = __float2half_rn(w[i - Sx]);
        else                  ow16[i - Sx - Sw] = __float2half_rn(ow[i - Sx - Sw]);
    }
}

// den[r] = sum_p dnp[p][r]  (deterministic fixed-order sum)
__global__ void dnred_k(const float* __restrict__ dnp, float* __restrict__ dn)
{
    const int r = blockIdx.x * blockDim.x + threadIdx.x;
    if (r < DNROWS) {
        float s = 0.f;
#pragma unroll
        for (int p = 0; p < 32; p++) s += dnp[(size_t)p * DNROWS + r];
        dn[r] = s;
    }
}

// ---------------------------------------------------------------------------
extern "C" void kernel_launch(void* const* d_in, const int* in_sizes, int n_in,
                              void* d_out, int out_size)
{
    const float* x  = (const float*)d_in[0];
    const float* w  = (const float*)d_in[1];
    const float* ow = (const float*)d_in[2];
    const float* ob = (const float*)d_in[3];
    float* out = (float*)d_out;

    f16 *x16, *w16, *ow16, *P16, *S, *M, *u16;
    float *dnp, *dn;
    cudaGetSymbolAddress((void**)&x16,  g_x16);
    cudaGetSymbolAddress((void**)&w16,  g_w16);
    cudaGetSymbolAddress((void**)&ow16, g_ow16);
    cudaGetSymbolAddress((void**)&P16,  g_P16);
    cudaGetSymbolAddress((void**)&S,    g_S);
    cudaGetSymbolAddress((void**)&M,    g_M);
    cudaGetSymbolAddress((void**)&dnp,  g_dnp);
    cudaGetSymbolAddress((void**)&dn,   g_dn);
    cudaGetSymbolAddress((void**)&u16,  g_u16);

    const size_t sP  = (size_t)CN * C5;
    const size_t sNN = (size_t)CN * CN;
    f16* X  = S;
    f16* Y  = S + (size_t)CB * sNN;
    f16* Zt = S + (size_t)2 * CB * sNN;
    f16* M1 = M;
    f16* M2 = M + (size_t)CB * sNN;

    cudaFuncSetAttribute(gemm64<0, false, false, false, false, false, false, f16>,
                         cudaFuncAttributeMaxDynamicSharedMemorySize, SMEM_64);
    cudaFuncSetAttribute(gemm64<1, false, true, false, false, false, false, f16>,
                         cudaFuncAttributeMaxDynamicSharedMemorySize, SMEM_64);
    cudaFuncSetAttribute(gemm64<0, true, false, false, true, false, false, f16>,
                         cudaFuncAttributeMaxDynamicSharedMemorySize, SMEM_64);
    cudaFuncSetAttribute(gemm64<0, false, false, false, true, true, false, f16>,
                         cudaFuncAttributeMaxDynamicSharedMemorySize, SMEM_64);
    cudaFuncSetAttribute(gemm64<2, true, false, false, false, false, true, f16>,
                         cudaFuncAttributeMaxDynamicSharedMemorySize, SMEM_64);
    cudaFuncSetAttribute(gemm64<0, false, false, true, false, false, false, float>,
                         cudaFuncAttributeMaxDynamicSharedMemorySize, SMEM_64);

    const float scale = 1.0f / sqrtf((float)CD);

    // 0. round inputs to fp16
    prep_k<<<592, 256>>>(x, w, ow, x16, w16, ow16);

    // 1. P = x @ w^T   (NT, K=512)
    gemm64<0, false, false, false, false, false, false, f16>
        <<<dim3(C5 / BN, (CB * CN) / BM, 1), 256, SMEM_64>>>(
        x16, w16, P16, nullptr, nullptr, nullptr,
        CD, CD, CD, C5, 0, 0, 0, 1.f, nullptr);

    // 2. Merged scores (NT, K=512): op0 X=exp(s a·b^T), op1 Y=exp(s b·c^T),
    //    op2 Zt=exp(s a·c^T)
    gemm64<1, false, true, false, false, false, false, f16>
        <<<dim3(CN / BN, CN / BM, 3 * CB), 256, SMEM_64>>>(
        P16, P16, S, nullptr, nullptr, nullptr,
        CD, C5, C5, CN, sP, sP, sNN, scale, nullptr);

    // 3. M2 = (X@Y) .* Zt   (NN, K=2048, fused multiply)
    gemm64<0, true, false, false, true, false, false, f16>
        <<<dim3(CN / BN, CN / BM, CB), 256, SMEM_64>>>(
        X, Y, M2, Zt, nullptr, nullptr,
        CN, CN, CN, CN, sNN, sNN, sNN, 1.f, nullptr);

    // 4. M1 = X .* NT(Zt,Y)   (NT, K=2048, fused multiply + row partials)
    gemm64<0, false, false, false, true, true, false, f16>
        <<<dim3(CN / BN, CN / BM, CB), 256, SMEM_64>>>(
        Zt, Y, M1, X, dnp, nullptr,
        CN, CN, CN, CN, sNN, sNN, sNN, 1.f, nullptr);

    // 5. den = reduce(dnp)
    dnred_k<<<(DNROWS + 255) / 256, 256>>>(dnp, dn);

    // 6. Merged u (NN, K=2048): op0 u[:,:512]=(M1@v1)/den, op1 u[:,512:]=(M2@v2)/den
    gemm64<2, true, false, false, false, false, true, f16>
        <<<dim3(CD / BN, CN / BM, 2 * CB), 256, SMEM_64>>>(
        M, P16, u16, nullptr, nullptr, dn,
        CN, CN, C5, C2, sNN, sP, (size_t)CN * C2, 1.f, nullptr);

    // 7. out = NT(u, ow) + ob   (NT, K=1024, f32 out)
    gemm64<0, false, false, true, false, false, false, float>
        <<<dim3(CD / BN, (CB * CN) / BM, 1), 256, SMEM_64>>>(
        u16, ow16, out, nullptr, nullptr, nullptr,
        C2, C2, C2, CD, 0, 0, 0, 1.f, ob);
}